// round 1
// baseline (speedup 1.0000x reference)
#include <cuda_runtime.h>

#define NQ 4
#define NL 2

// Precomputed batch-invariant constants, filled by setup_kernel each launch.
struct Consts {
    float wc[NL][NQ];   // cos(weights/2)
    float ws[NL][NQ];   // sin(weights/2)
    float g[2][16];     // folded Z-sign * W head:  g[j][s] = sum_i W[j,i]*sign_i(s)
    float b[2];
};
__device__ Consts g_consts;

__global__ void setup_kernel(const float* __restrict__ weights,
                             const float* __restrict__ W,
                             const float* __restrict__ b) {
    if (threadIdx.x == 0 && blockIdx.x == 0) {
        for (int l = 0; l < NL; ++l) {
            for (int i = 0; i < NQ; ++i) {
                float h = 0.5f * weights[l * NQ + i];
                g_consts.wc[l][i] = cosf(h);
                g_consts.ws[l][i] = sinf(h);
            }
        }
        for (int j = 0; j < 2; ++j) {
            for (int s = 0; s < 16; ++s) {
                float acc = 0.0f;
                for (int q = 0; q < NQ; ++q) {
                    // qubit q owns bit (3-q): state index s = b0*8 + b1*4 + b2*2 + b3
                    float sign = ((s >> (3 - q)) & 1) ? -1.0f : 1.0f;
                    acc = fmaf(W[j * NQ + q], sign, acc);
                }
                g_consts.g[j][s] = acc;
            }
            g_consts.b[j] = b[j];
        }
    }
}

// RY with compile-time qubit index; c,s uniform-per-launch constants.
__device__ __forceinline__ void ry_const(float a[16], int q, float c, float s) {
    const int m = 1 << (3 - q);
#pragma unroll
    for (int idx = 0; idx < 16; ++idx) {
        if (!(idx & m)) {
            float a0 = a[idx];
            float a1 = a[idx | m];
            a[idx]     = fmaf(c, a0, -s * a1);
            a[idx | m] = fmaf(s, a0,  c * a1);
        }
    }
}

// CNOT: pure register permutation after full unroll.
__device__ __forceinline__ void cnot(float a[16], int ctrl, int tgt) {
    const int mc = 1 << (3 - ctrl);
    const int mt = 1 << (3 - tgt);
#pragma unroll
    for (int s = 0; s < 16; ++s) {
        if ((s & mc) && !(s & mt)) {
            float tmp = a[s];
            a[s] = a[s | mt];
            a[s | mt] = tmp;
        }
    }
}

__global__ __launch_bounds__(256)
void sim_kernel(const float4* __restrict__ x, float2* __restrict__ out, int B) {
    int i = blockIdx.x * blockDim.x + threadIdx.x;
    if (i >= B) return;

    float4 xi = x[i];

    float c0, s0, c1, s1, c2, s2, c3, s3;
    __sincosf(0.5f * xi.x, &s0, &c0);
    __sincosf(0.5f * xi.y, &s1, &c1);
    __sincosf(0.5f * xi.z, &s2, &c2);
    __sincosf(0.5f * xi.w, &s3, &c3);

    // Product state |psi> = RY(x3)RY(x2)RY(x1)RY(x0)|0000>, built by tensor expansion.
    float a[16];
    a[0] = c0;
    a[8] = s0;
    // qubit 1 (bit 2)
    a[4]  = a[0] * s1;  a[12] = a[8] * s1;
    a[0]  = a[0] * c1;  a[8]  = a[8] * c1;
    // qubit 2 (bit 1)
#pragma unroll
    for (int k = 0; k < 16; k += 4) {
        a[k + 2] = a[k] * s2;
        a[k]     = a[k] * c2;
    }
    // qubit 3 (bit 0)
#pragma unroll
    for (int k = 0; k < 16; k += 2) {
        a[k + 1] = a[k] * s3;
        a[k]     = a[k] * c3;
    }

    // Entangling layers: CNOT ring then constant-angle RYs.
#pragma unroll
    for (int l = 0; l < NL; ++l) {
        cnot(a, 0, 1);
        cnot(a, 1, 2);
        cnot(a, 2, 3);
        cnot(a, 3, 0);
#pragma unroll
        for (int q = 0; q < NQ; ++q) {
            ry_const(a, q, g_consts.wc[l][q], g_consts.ws[l][q]);
        }
    }

    // Fused epilogue: out_j = b_j + sum_s g[j][s] * a[s]^2
    float o0 = g_consts.b[0];
    float o1 = g_consts.b[1];
#pragma unroll
    for (int s = 0; s < 16; ++s) {
        float p = a[s] * a[s];
        o0 = fmaf(g_consts.g[0][s], p, o0);
        o1 = fmaf(g_consts.g[1][s], p, o1);
    }

    out[i] = make_float2(o0, o1);
}

extern "C" void kernel_launch(void* const* d_in, const int* in_sizes, int n_in,
                              void* d_out, int out_size) {
    const float* x       = (const float*)d_in[0];  // (B, 4)
    const float* weights = (const float*)d_in[1];  // (2, 4)
    const float* W       = (const float*)d_in[2];  // (2, 4)
    const float* b       = (const float*)d_in[3];  // (2,)

    int B = in_sizes[0] / NQ;

    setup_kernel<<<1, 32>>>(weights, W, b);
    sim_kernel<<<(B + 255) / 256, 256>>>((const float4*)x, (float2*)d_out, B);
}

// round 2
// speedup vs baseline: 1.1418x; 1.1418x over previous
#include <cuda_runtime.h>

#define NQ 4
#define NL 2

typedef unsigned long long u64;

// ---------------- packed f32x2 helpers (sm_103a) ----------------
__device__ __forceinline__ u64 pk2(float lo, float hi) {
    u64 r;
    asm("mov.b64 %0, {%1, %2};" : "=l"(r) : "f"(lo), "f"(hi));
    return r;
}
__device__ __forceinline__ void unpk2(u64 v, float& lo, float& hi) {
    asm("mov.b64 {%0, %1}, %2;" : "=f"(lo), "=f"(hi) : "l"(v));
}
__device__ __forceinline__ u64 mul2(u64 a, u64 b) {
    u64 r;
    asm("mul.rn.f32x2 %0, %1, %2;" : "=l"(r) : "l"(a), "l"(b));
    return r;
}
__device__ __forceinline__ u64 fma2(u64 a, u64 b, u64 c) {
    u64 r;
    asm("fma.rn.f32x2 %0, %1, %2, %3;" : "=l"(r) : "l"(a), "l"(b), "l"(c));
    return r;
}

// Batch-invariant constants, pre-duplicated into both f32x2 lanes.
struct Consts {
    u64 cc[NL][NQ];   // (cos(w/2), cos(w/2))
    u64 ss[NL][NQ];   // (sin(w/2), sin(w/2))
    u64 sn[NL][NQ];   // (-sin(w/2), -sin(w/2))
    u64 g0[16];       // folded head row 0, duplicated
    u64 g1[16];       // folded head row 1, duplicated
    u64 b0, b1;
};
__device__ Consts g_consts;

__global__ void setup_kernel(const float* __restrict__ weights,
                             const float* __restrict__ W,
                             const float* __restrict__ b) {
    if (threadIdx.x == 0 && blockIdx.x == 0) {
        for (int l = 0; l < NL; ++l) {
            for (int i = 0; i < NQ; ++i) {
                float h = 0.5f * weights[l * NQ + i];
                float c = cosf(h), s = sinf(h);
                g_consts.cc[l][i] = pk2(c, c);
                g_consts.ss[l][i] = pk2(s, s);
                g_consts.sn[l][i] = pk2(-s, -s);
            }
        }
        for (int s = 0; s < 16; ++s) {
            float acc0 = 0.0f, acc1 = 0.0f;
            for (int q = 0; q < NQ; ++q) {
                float sign = ((s >> (3 - q)) & 1) ? -1.0f : 1.0f;
                acc0 = fmaf(W[0 * NQ + q], sign, acc0);
                acc1 = fmaf(W[1 * NQ + q], sign, acc1);
            }
            g_consts.g0[s] = pk2(acc0, acc0);
            g_consts.g1[s] = pk2(acc1, acc1);
        }
        g_consts.b0 = pk2(b[0], b[0]);
        g_consts.b1 = pk2(b[1], b[1]);
    }
}

// RY on qubit q (compile-time), packed over 2 samples.
__device__ __forceinline__ void ry2(u64 a[16], int q, u64 cc, u64 ss, u64 sn) {
    const int m = 1 << (3 - q);
#pragma unroll
    for (int idx = 0; idx < 16; ++idx) {
        if (!(idx & m)) {
            u64 a0 = a[idx];
            u64 a1 = a[idx | m];
            a[idx]     = fma2(cc, a0, mul2(sn, a1));
            a[idx | m] = fma2(ss, a0, mul2(cc, a1));
        }
    }
}

// CNOT: compile-time register permutation (no instructions after unroll).
__device__ __forceinline__ void cnot2(u64 a[16], int ctrl, int tgt) {
    const int mc = 1 << (3 - ctrl);
    const int mt = 1 << (3 - tgt);
#pragma unroll
    for (int s = 0; s < 16; ++s) {
        if ((s & mc) && !(s & mt)) {
            u64 tmp = a[s];
            a[s] = a[s | mt];
            a[s | mt] = tmp;
        }
    }
}

__global__ __launch_bounds__(256)
void sim_kernel(const float4* __restrict__ x, float4* __restrict__ out, int Bpair) {
    int t = blockIdx.x * blockDim.x + threadIdx.x;
    if (t >= Bpair) return;

    // Two samples per thread: 2t (lane lo) and 2t+1 (lane hi).
    float4 xa = x[2 * t];
    float4 xb = x[2 * t + 1];

    float c0a, s0a, c1a, s1a, c2a, s2a, c3a, s3a;
    float c0b, s0b, c1b, s1b, c2b, s2b, c3b, s3b;
    __sincosf(0.5f * xa.x, &s0a, &c0a);
    __sincosf(0.5f * xa.y, &s1a, &c1a);
    __sincosf(0.5f * xa.z, &s2a, &c2a);
    __sincosf(0.5f * xa.w, &s3a, &c3a);
    __sincosf(0.5f * xb.x, &s0b, &c0b);
    __sincosf(0.5f * xb.y, &s1b, &c1b);
    __sincosf(0.5f * xb.z, &s2b, &c2b);
    __sincosf(0.5f * xb.w, &s3b, &c3b);

    u64 c0 = pk2(c0a, c0b), s0 = pk2(s0a, s0b);
    u64 c1 = pk2(c1a, c1b), s1 = pk2(s1a, s1b);
    u64 c2 = pk2(c2a, c2b), s2 = pk2(s2a, s2b);
    u64 c3 = pk2(c3a, c3b), s3 = pk2(s3a, s3b);

    // Product state via tensor expansion (muls only).
    u64 a[16];
    a[0] = c0;
    a[8] = s0;
    a[4]  = mul2(a[0], s1);  a[12] = mul2(a[8], s1);
    a[0]  = mul2(a[0], c1);  a[8]  = mul2(a[8], c1);
#pragma unroll
    for (int k = 0; k < 16; k += 4) {
        a[k + 2] = mul2(a[k], s2);
        a[k]     = mul2(a[k], c2);
    }
#pragma unroll
    for (int k = 0; k < 16; k += 2) {
        a[k + 1] = mul2(a[k], s3);
        a[k]     = mul2(a[k], c3);
    }

    // Entangling layers.
#pragma unroll
    for (int l = 0; l < NL; ++l) {
        cnot2(a, 0, 1);
        cnot2(a, 1, 2);
        cnot2(a, 2, 3);
        cnot2(a, 3, 0);
#pragma unroll
        for (int q = 0; q < NQ; ++q) {
            ry2(a, q, g_consts.cc[l][q], g_consts.ss[l][q], g_consts.sn[l][q]);
        }
    }

    // Epilogue: o_j = b_j + sum_s g_j[s] * a[s]^2, both lanes at once.
    u64 acc0 = g_consts.b0;
    u64 acc1 = g_consts.b1;
#pragma unroll
    for (int s = 0; s < 16; ++s) {
        u64 p = mul2(a[s], a[s]);
        acc0 = fma2(g_consts.g0[s], p, acc0);
        acc1 = fma2(g_consts.g1[s], p, acc1);
    }

    float o0a, o0b, o1a, o1b;
    unpk2(acc0, o0a, o0b);
    unpk2(acc1, o1a, o1b);

    // Samples 2t and 2t+1, each float2 -> one float4 store.
    out[t] = make_float4(o0a, o1a, o0b, o1b);
}

extern "C" void kernel_launch(void* const* d_in, const int* in_sizes, int n_in,
                              void* d_out, int out_size) {
    const float* x       = (const float*)d_in[0];  // (B, 4)
    const float* weights = (const float*)d_in[1];  // (2, 4)
    const float* W       = (const float*)d_in[2];  // (2, 4)
    const float* b       = (const float*)d_in[3];  // (2,)

    int B = in_sizes[0] / NQ;
    int Bpair = B / 2;  // B = 2^21, even

    setup_kernel<<<1, 32>>>(weights, W, b);
    sim_kernel<<<(Bpair + 255) / 256, 256>>>((const float4*)x, (float4*)d_out, Bpair);
}

// round 3
// speedup vs baseline: 1.3007x; 1.1392x over previous
#include <cuda_runtime.h>

#define NQ 4
#define NL 2

typedef unsigned long long u64;

// ---------------- packed f32x2 helpers (sm_103a) ----------------
__device__ __forceinline__ u64 pk2(float lo, float hi) {
    u64 r;
    asm("mov.b64 %0, {%1, %2};" : "=l"(r) : "f"(lo), "f"(hi));
    return r;
}
__device__ __forceinline__ void unpk2(u64 v, float& lo, float& hi) {
    asm("mov.b64 {%0, %1}, %2;" : "=f"(lo), "=f"(hi) : "l"(v));
}
__device__ __forceinline__ u64 mul2(u64 a, u64 b) {
    u64 r;
    asm("mul.rn.f32x2 %0, %1, %2;" : "=l"(r) : "l"(a), "l"(b));
    return r;
}
__device__ __forceinline__ u64 fma2(u64 a, u64 b, u64 c) {
    u64 r;
    asm("fma.rn.f32x2 %0, %1, %2, %3;" : "=l"(r) : "l"(a), "l"(b), "l"(c));
    return r;
}

// Batch-invariant constants (tan-form gates, duplicated into both lanes).
// Constant RY(w) = cos(w/2) * [[1,-t],[t,1]], t = tan(w/2). The scalar
// C = prod cos(w/2) over all 8 gates is folded into g via g *= C^2
// (probabilities are quadratic in the state).
struct Consts {
    u64 tp[NL][NQ];   // (+t, +t)
    u64 tn[NL][NQ];   // (-t, -t)
    u64 g0[16];       // C^2 * folded head row 0
    u64 g1[16];       // C^2 * folded head row 1
    u64 b0, b1;
};
__device__ Consts g_consts;

__global__ void setup_kernel(const float* __restrict__ weights,
                             const float* __restrict__ W,
                             const float* __restrict__ b) {
    if (threadIdx.x == 0 && blockIdx.x == 0) {
        float C = 1.0f;
        for (int l = 0; l < NL; ++l) {
            for (int i = 0; i < NQ; ++i) {
                float h = 0.5f * weights[l * NQ + i];
                float c = cosf(h), s = sinf(h);
                float t = s / c;
                C *= c;
                g_consts.tp[l][i] = pk2(t, t);
                g_consts.tn[l][i] = pk2(-t, -t);
            }
        }
        float C2 = C * C;
        for (int s = 0; s < 16; ++s) {
            float acc0 = 0.0f, acc1 = 0.0f;
            for (int q = 0; q < NQ; ++q) {
                float sign = ((s >> (3 - q)) & 1) ? -1.0f : 1.0f;
                acc0 = fmaf(W[0 * NQ + q], sign, acc0);
                acc1 = fmaf(W[1 * NQ + q], sign, acc1);
            }
            g_consts.g0[s] = pk2(C2 * acc0, C2 * acc0);
            g_consts.g1[s] = pk2(C2 * acc1, C2 * acc1);
        }
        g_consts.b0 = pk2(b[0], b[0]);
        g_consts.b1 = pk2(b[1], b[1]);
    }
}

// tan-form RY on qubit q: a0' = a0 - t*a1 ; a1' = a1 + t*a0   (2 fma per pair)
__device__ __forceinline__ void ry_tan(u64 a[16], int q, u64 tp, u64 tn) {
    const int m = 1 << (3 - q);
#pragma unroll
    for (int idx = 0; idx < 16; ++idx) {
        if (!(idx & m)) {
            u64 a0 = a[idx];
            u64 a1 = a[idx | m];
            a[idx]     = fma2(tn, a1, a0);
            a[idx | m] = fma2(tp, a0, a1);
        }
    }
}

// CNOT: compile-time register permutation (zero instructions after unroll).
__device__ __forceinline__ void cnot2(u64 a[16], int ctrl, int tgt) {
    const int mc = 1 << (3 - ctrl);
    const int mt = 1 << (3 - tgt);
#pragma unroll
    for (int s = 0; s < 16; ++s) {
        if ((s & mc) && !(s & mt)) {
            u64 tmp = a[s];
            a[s] = a[s | mt];
            a[s | mt] = tmp;
        }
    }
}

__global__ __launch_bounds__(256)
void sim_kernel(const float4* __restrict__ x, float4* __restrict__ out, int Bpair) {
    int t = blockIdx.x * blockDim.x + threadIdx.x;
    if (t >= Bpair) return;

    // Two samples per thread: 2t (lane lo) and 2t+1 (lane hi).
    float4 xa = x[2 * t];
    float4 xb = x[2 * t + 1];

    float c0a, s0a, c1a, s1a, c2a, s2a, c3a, s3a;
    float c0b, s0b, c1b, s1b, c2b, s2b, c3b, s3b;
    __sincosf(0.5f * xa.x, &s0a, &c0a);
    __sincosf(0.5f * xa.y, &s1a, &c1a);
    __sincosf(0.5f * xa.z, &s2a, &c2a);
    __sincosf(0.5f * xa.w, &s3a, &c3a);
    __sincosf(0.5f * xb.x, &s0b, &c0b);
    __sincosf(0.5f * xb.y, &s1b, &c1b);
    __sincosf(0.5f * xb.z, &s2b, &c2b);
    __sincosf(0.5f * xb.w, &s3b, &c3b);

    u64 c0 = pk2(c0a, c0b), s0 = pk2(s0a, s0b);
    u64 c1 = pk2(c1a, c1b), s1 = pk2(s1a, s1b);
    u64 c2 = pk2(c2a, c2b), s2 = pk2(s2a, s2b);
    u64 c3 = pk2(c3a, c3b), s3 = pk2(s3a, s3b);

    // Product state via tensor expansion (muls only; per-sample gates exact).
    u64 a[16];
    a[0] = c0;
    a[8] = s0;
    a[4]  = mul2(a[0], s1);  a[12] = mul2(a[8], s1);
    a[0]  = mul2(a[0], c1);  a[8]  = mul2(a[8], c1);
#pragma unroll
    for (int k = 0; k < 16; k += 4) {
        a[k + 2] = mul2(a[k], s2);
        a[k]     = mul2(a[k], c2);
    }
#pragma unroll
    for (int k = 0; k < 16; k += 2) {
        a[k + 1] = mul2(a[k], s3);
        a[k]     = mul2(a[k], c3);
    }

    // Entangling layers: CNOT ring (free) + tan-form constant RYs (2 fma2/pair).
#pragma unroll
    for (int l = 0; l < NL; ++l) {
        cnot2(a, 0, 1);
        cnot2(a, 1, 2);
        cnot2(a, 2, 3);
        cnot2(a, 3, 0);
#pragma unroll
        for (int q = 0; q < NQ; ++q) {
            ry_tan(a, q, g_consts.tp[l][q], g_consts.tn[l][q]);
        }
    }

    // Epilogue: o_j = b_j + sum_s (C^2 g_j[s]) * a[s]^2, both lanes at once.
    u64 acc0 = g_consts.b0;
    u64 acc1 = g_consts.b1;
#pragma unroll
    for (int s = 0; s < 16; ++s) {
        u64 p = mul2(a[s], a[s]);
        acc0 = fma2(g_consts.g0[s], p, acc0);
        acc1 = fma2(g_consts.g1[s], p, acc1);
    }

    float o0a, o0b, o1a, o1b;
    unpk2(acc0, o0a, o0b);
    unpk2(acc1, o1a, o1b);

    out[t] = make_float4(o0a, o1a, o0b, o1b);
}

extern "C" void kernel_launch(void* const* d_in, const int* in_sizes, int n_in,
                              void* d_out, int out_size) {
    const float* x       = (const float*)d_in[0];  // (B, 4)
    const float* weights = (const float*)d_in[1];  // (2, 4)
    const float* W       = (const float*)d_in[2];  // (2, 4)
    const float* b       = (const float*)d_in[3];  // (2,)

    int B = in_sizes[0] / NQ;
    int Bpair = B / 2;

    setup_kernel<<<1, 32>>>(weights, W, b);
    sim_kernel<<<(Bpair + 255) / 256, 256>>>((const float4*)x, (float4*)d_out, Bpair);
}

// round 4
// speedup vs baseline: 1.6814x; 1.2927x over previous
#include <cuda_runtime.h>

#define NQ 4
#define NL 2

typedef unsigned long long u64;

// ---------------- packed f32x2 helpers (sm_103a) ----------------
__device__ __forceinline__ u64 pk2(float lo, float hi) {
    u64 r;
    asm("mov.b64 %0, {%1, %2};" : "=l"(r) : "f"(lo), "f"(hi));
    return r;
}
__device__ __forceinline__ void unpk2(u64 v, float& lo, float& hi) {
    asm("mov.b64 {%0, %1}, %2;" : "=f"(lo), "=f"(hi) : "l"(v));
}
__device__ __forceinline__ u64 mul2(u64 a, u64 b) {
    u64 r;
    asm("mul.rn.f32x2 %0, %1, %2;" : "=l"(r) : "l"(a), "l"(b));
    return r;
}
__device__ __forceinline__ u64 fma2(u64 a, u64 b, u64 c) {
    u64 r;
    asm("fma.rn.f32x2 %0, %1, %2, %3;" : "=l"(r) : "l"(a), "l"(b), "l"(c));
    return r;
}

// Batch-invariant constants (both f32x2 lanes duplicated).
//  - Layer-0 RYs in tan form: RY(w)=cos(w/2)[[1,-t],[t,1]]; scalar C'=prod cos(w/2)
//    folded (as C'^2) into the measurement coefficients.
//  - Layer-1 RYs absorbed into measurement: RY(th)^T Z RY(th) = cos(th) Z - sin(th) X.
//    h_j[s] = C'^2 * sum_i W[j,i] cos(w1_i) sign_i(s)     (Z part, on squares)
//    v_j[i] = -2 C'^2 * W[j,i] sin(w1_i)                  (X part, on cross terms)
struct Consts {
    u64 tp[NQ];    // (+tan(w0_i/2))
    u64 tn[NQ];    // (-tan(w0_i/2))
    u64 h0[16];    // Z-part coeffs, head row 0
    u64 h1[16];    // Z-part coeffs, head row 1
    u64 v0[NQ];    // X-part coeffs, head row 0
    u64 v1[NQ];    // X-part coeffs, head row 1
    u64 b0, b1;
};

__device__ Consts g_scratch;          // written by setup_kernel
__constant__ Consts c_consts;         // filled via D2D memcpy; read via constant port

__global__ void setup_kernel(const float* __restrict__ weights,
                             const float* __restrict__ W,
                             const float* __restrict__ b) {
    if (threadIdx.x == 0 && blockIdx.x == 0) {
        float C = 1.0f;
        for (int i = 0; i < NQ; ++i) {
            float h = 0.5f * weights[i];          // layer 0
            float c = cosf(h), s = sinf(h);
            float t = s / c;
            C *= c;
            g_scratch.tp[i] = pk2(t, t);
            g_scratch.tn[i] = pk2(-t, -t);
        }
        float C2 = C * C;
        float c1[NQ], s1[NQ];
        for (int i = 0; i < NQ; ++i) {
            c1[i] = cosf(weights[NQ + i]);        // layer 1, full angle
            s1[i] = sinf(weights[NQ + i]);
        }
        for (int s = 0; s < 16; ++s) {
            float a0 = 0.0f, a1 = 0.0f;
            for (int i = 0; i < NQ; ++i) {
                float sign = ((s >> (3 - i)) & 1) ? -1.0f : 1.0f;
                a0 += W[0 * NQ + i] * c1[i] * sign;
                a1 += W[1 * NQ + i] * c1[i] * sign;
            }
            g_scratch.h0[s] = pk2(C2 * a0, C2 * a0);
            g_scratch.h1[s] = pk2(C2 * a1, C2 * a1);
        }
        for (int i = 0; i < NQ; ++i) {
            float u0 = -2.0f * C2 * W[0 * NQ + i] * s1[i];
            float u1 = -2.0f * C2 * W[1 * NQ + i] * s1[i];
            g_scratch.v0[i] = pk2(u0, u0);
            g_scratch.v1[i] = pk2(u1, u1);
        }
        g_scratch.b0 = pk2(b[0], b[0]);
        g_scratch.b1 = pk2(b[1], b[1]);
    }
}

// tan-form RY on qubit q: a0' = a0 - t*a1 ; a1' = a1 + t*a0
__device__ __forceinline__ void ry_tan(u64 a[16], int q, u64 tp, u64 tn) {
    const int m = 1 << (3 - q);
#pragma unroll
    for (int idx = 0; idx < 16; ++idx) {
        if (!(idx & m)) {
            u64 a0 = a[idx];
            u64 a1 = a[idx | m];
            a[idx]     = fma2(tn, a1, a0);
            a[idx | m] = fma2(tp, a0, a1);
        }
    }
}

// CNOT: compile-time register permutation (zero instructions after unroll).
__device__ __forceinline__ void cnot2(u64 a[16], int ctrl, int tgt) {
    const int mc = 1 << (3 - ctrl);
    const int mt = 1 << (3 - tgt);
#pragma unroll
    for (int s = 0; s < 16; ++s) {
        if ((s & mc) && !(s & mt)) {
            u64 tmp = a[s];
            a[s] = a[s | mt];
            a[s | mt] = tmp;
        }
    }
}

__global__ __launch_bounds__(256)
void sim_kernel(const float4* __restrict__ x, float4* __restrict__ out, int Bpair) {
    int t = blockIdx.x * blockDim.x + threadIdx.x;
    if (t >= Bpair) return;

    float4 xa = x[2 * t];
    float4 xb = x[2 * t + 1];

    float c0a, s0a, c1a, s1a, c2a, s2a, c3a, s3a;
    float c0b, s0b, c1b, s1b, c2b, s2b, c3b, s3b;
    __sincosf(0.5f * xa.x, &s0a, &c0a);
    __sincosf(0.5f * xa.y, &s1a, &c1a);
    __sincosf(0.5f * xa.z, &s2a, &c2a);
    __sincosf(0.5f * xa.w, &s3a, &c3a);
    __sincosf(0.5f * xb.x, &s0b, &c0b);
    __sincosf(0.5f * xb.y, &s1b, &c1b);
    __sincosf(0.5f * xb.z, &s2b, &c2b);
    __sincosf(0.5f * xb.w, &s3b, &c3b);

    u64 c0 = pk2(c0a, c0b), s0 = pk2(s0a, s0b);
    u64 c1 = pk2(c1a, c1b), s1 = pk2(s1a, s1b);
    u64 c2 = pk2(c2a, c2b), s2 = pk2(s2a, s2b);
    u64 c3 = pk2(c3a, c3b), s3 = pk2(s3a, s3b);

    // Product state via tensor expansion (28 muls).
    u64 a[16];
    a[0] = c0;
    a[8] = s0;
    a[4]  = mul2(a[0], s1);  a[12] = mul2(a[8], s1);
    a[0]  = mul2(a[0], c1);  a[8]  = mul2(a[8], c1);
#pragma unroll
    for (int k = 0; k < 16; k += 4) {
        a[k + 2] = mul2(a[k], s2);
        a[k]     = mul2(a[k], c2);
    }
#pragma unroll
    for (int k = 0; k < 16; k += 2) {
        a[k + 1] = mul2(a[k], s3);
        a[k]     = mul2(a[k], c3);
    }

    // Layer 0: CNOT ring (free) + tan-form RYs.
    cnot2(a, 0, 1);
    cnot2(a, 1, 2);
    cnot2(a, 2, 3);
    cnot2(a, 3, 0);
#pragma unroll
    for (int q = 0; q < NQ; ++q) {
        ry_tan(a, q, c_consts.tp[q], c_consts.tn[q]);
    }

    // Layer 1: CNOT ring (free); RYs absorbed into the measurement below.
    cnot2(a, 0, 1);
    cnot2(a, 1, 2);
    cnot2(a, 2, 3);
    cnot2(a, 3, 0);

    // Measurement: o_j = b_j + sum_s h_j[s] a_s^2 + sum_i v_j[i] * y_i,
    // with y_i = sum over pairs a_s * a_{s^m_i}   (X_i cross terms, factor 2 folded).
    u64 acc0 = c_consts.b0;
    u64 acc1 = c_consts.b1;
#pragma unroll
    for (int s = 0; s < 16; ++s) {
        u64 p = mul2(a[s], a[s]);
        acc0 = fma2(c_consts.h0[s], p, acc0);
        acc1 = fma2(c_consts.h1[s], p, acc1);
    }
#pragma unroll
    for (int i = 0; i < NQ; ++i) {
        const int m = 8 >> i;
        u64 y;
        bool first = true;
#pragma unroll
        for (int s = 0; s < 16; ++s) {
            if (!(s & m)) {
                if (first) { y = mul2(a[s], a[s | m]); first = false; }
                else       { y = fma2(a[s], a[s | m], y); }
            }
        }
        acc0 = fma2(c_consts.v0[i], y, acc0);
        acc1 = fma2(c_consts.v1[i], y, acc1);
    }

    float o0a, o0b, o1a, o1b;
    unpk2(acc0, o0a, o0b);
    unpk2(acc1, o1a, o1b);

    out[t] = make_float4(o0a, o1a, o0b, o1b);
}

extern "C" void kernel_launch(void* const* d_in, const int* in_sizes, int n_in,
                              void* d_out, int out_size) {
    const float* x       = (const float*)d_in[0];  // (B, 4)
    const float* weights = (const float*)d_in[1];  // (2, 4)
    const float* W       = (const float*)d_in[2];  // (2, 4)
    const float* b       = (const float*)d_in[3];  // (2,)

    int B = in_sizes[0] / NQ;
    int Bpair = B / 2;

    setup_kernel<<<1, 32>>>(weights, W, b);

    // Publish the computed constants to the constant bank (capturable D2D memcpy).
    void* dst = nullptr;
    void* src = nullptr;
    cudaGetSymbolAddress(&dst, c_consts);
    cudaGetSymbolAddress(&src, g_scratch);
    cudaMemcpyAsync(dst, src, sizeof(Consts), cudaMemcpyDeviceToDevice, 0);

    sim_kernel<<<(Bpair + 255) / 256, 256>>>((const float4*)x, (float4*)d_out, Bpair);
}